// round 7
// baseline (speedup 1.0000x reference)
#include <cuda_runtime.h>
#include <cuda_fp16.h>
#include <cstdint>

// Sparse embedding-bag: out[b,:] = bias + sum_k weight[ft_ics[b,k],:] * ft_vals[b,k]
// B=16384, K=32, N_OUT=256. Table 41024x256 fp32 = 42 MB.
//
// R7: fp16 table pre-pass + LATENCY attack in the gather: K split across a
// warp PAIR per batch row (16 feats each) -> serial dependent phases per warp
// halved (8 -> 4), warps doubled (32768) for 2x chip-wide load concurrency.
// Partials combined via smem. FFMA2 packed math kept for issue headroom.

#define N_IN_ROWS 41024
#define N_OUT_COLS 256
#define K_FEATS 32
#define K_HALF 16
#define WARPS_PER_BLOCK 8     // 4 rows x 2 k-halves
#define ROWS_PER_BLOCK 4
#define KU 4

__device__ __half g_w16[(size_t)N_IN_ROWS * N_OUT_COLS];

// ---------------- conversion: fp32 table -> fp16 table (streaming) ----------
__global__ __launch_bounds__(256)
void convert_w16_kernel(const float4* __restrict__ w32)
{
    const size_t n4 = (size_t)N_IN_ROWS * N_OUT_COLS / 4;
    uint2* dst = reinterpret_cast<uint2*>(g_w16);
    for (size_t i = (size_t)blockIdx.x * blockDim.x + threadIdx.x;
         i < n4; i += (size_t)gridDim.x * blockDim.x) {
        const float4 w = __ldg(&w32[i]);
        __half2 h0 = __floats2half2_rn(w.x, w.y);
        __half2 h1 = __floats2half2_rn(w.z, w.w);
        uint2 u;
        u.x = *reinterpret_cast<unsigned*>(&h0);
        u.y = *reinterpret_cast<unsigned*>(&h1);
        dst[i] = u;
    }
}

// cvt half2 -> packed f32x2, then packed FFMA2 into a b64 accumulator.
__device__ __forceinline__ void fma2_h2(unsigned long long& acc, unsigned h2,
                                        unsigned long long vv)
{
    asm("{\n\t"
        ".reg .b16 hl, hh;\n\t"
        ".reg .f32 lo, hi;\n\t"
        ".reg .b64 w2;\n\t"
        "mov.b32 {hl, hh}, %1;\n\t"
        "cvt.f32.f16 lo, hl;\n\t"
        "cvt.f32.f16 hi, hh;\n\t"
        "mov.b64 w2, {lo, hi};\n\t"
        "fma.rn.f32x2 %0, %2, w2, %0;\n\t"
        "}"
        : "+l"(acc) : "r"(h2), "l"(vv));
}

__device__ __forceinline__ unsigned long long addf32x2(unsigned long long a,
                                                       unsigned long long b)
{
    unsigned long long r;
    asm("add.rn.f32x2 %0, %1, %2;" : "=l"(r) : "l"(a), "l"(b));
    return r;
}

// ---------------- gather: warp-pair per row, fp16 table ---------------------
// warp w: row = w/2, khalf = w%2 (features [khalf*16, khalf*16+16)).
// Lane tx owns column pairs {c*64+2tx, +1 : c=0..3}. 4 coalesced LDG.32 per
// feature; KU=4 front-batched -> 16 loads in flight; only 4 serial phases.
__global__ __launch_bounds__(32 * WARPS_PER_BLOCK, 6)
void ft_embed_bag_kernel(const int* __restrict__ ics,
                         const float* __restrict__ vals,
                         const float* __restrict__ bias,   // [256]
                         float* __restrict__ out)          // [B][256]
{
    __shared__ uint2              s_iv[ROWS_PER_BLOCK][K_FEATS];
    __shared__ unsigned long long s_part[ROWS_PER_BLOCK][128];  // 256 floats/row

    const int tx    = threadIdx.x;
    const int wid   = threadIdx.y;
    const int row   = wid >> 1;            // row within block
    const int khalf = wid & 1;
    const int b     = blockIdx.x * ROWS_PER_BLOCK + row;

    // Per-warp staging: lanes 0..15 fetch this half's (idx, val).
    if (tx < K_HALF) {
        const int   f   = khalf * K_HALF + tx;
        const int   raw = __ldg(&ics[b * K_FEATS + f]);
        const float v   = __ldg(&vals[b * K_FEATS + f]);
        const bool valid = (raw >= 0);
        uint2 iv;
        iv.x = valid ? (unsigned)raw : 0u;
        iv.y = valid ? __float_as_uint(v) : 0u;
        s_iv[row][f] = iv;
    }
    __syncwarp();

    // Packed accumulators: khalf 0 seeds with bias, khalf 1 with zero.
    unsigned long long acc2[4];
    if (khalf == 0) {
        const float2* b2 = reinterpret_cast<const float2*>(bias);
        #pragma unroll
        for (int c = 0; c < 4; ++c) {
            const float2 bv = __ldg(b2 + c * 32 + tx);
            asm("mov.b64 %0, {%1, %2};" : "=l"(acc2[c]) : "f"(bv.x), "f"(bv.y));
        }
    } else {
        #pragma unroll
        for (int c = 0; c < 4; ++c) acc2[c] = 0ull;
    }

    const __half2* wtab = reinterpret_cast<const __half2*>(g_w16);

    #pragma unroll
    for (int k0 = 0; k0 < K_HALF; k0 += KU) {
        unsigned           idx[KU];
        unsigned long long vv[KU];
        #pragma unroll
        for (int j = 0; j < KU; ++j) {
            const uint2 iv = s_iv[row][khalf * K_HALF + k0 + j];
            idx[j] = iv.x;
            const float v = __uint_as_float(iv.y);
            asm("mov.b64 %0, {%1, %1};" : "=l"(vv[j]) : "f"(v));
        }

        // Front-batch 4*KU independent coalesced LDG.32 (one 128B line each).
        unsigned w[KU][4];
        #pragma unroll
        for (int j = 0; j < KU; ++j) {
            const __half2* base = wtab + (size_t)idx[j] * 128 + tx;
            #pragma unroll
            for (int c = 0; c < 4; ++c)
                w[j][c] = __ldg(reinterpret_cast<const unsigned*>(base + c * 32));
        }

        #pragma unroll
        for (int j = 0; j < KU; ++j)
            #pragma unroll
            for (int c = 0; c < 4; ++c)
                fma2_h2(acc2[c], w[j][c], vv[j]);
    }

    // Combine the two halves through smem, khalf 0 stores to global.
    if (khalf == 1) {
        #pragma unroll
        for (int c = 0; c < 4; ++c)
            s_part[row][c * 32 + tx] = acc2[c];
    }
    __syncthreads();
    if (khalf == 0) {
        float* orow = out + (size_t)b * N_OUT_COLS;
        #pragma unroll
        for (int c = 0; c < 4; ++c) {
            const unsigned long long r = addf32x2(acc2[c], s_part[row][c * 32 + tx]);
            float* p = orow + c * 64 + 2 * tx;
            asm volatile("st.global.cs.b64 [%0], %1;" :: "l"(p), "l"(r));
        }
    }
}

extern "C" void kernel_launch(void* const* d_in, const int* in_sizes, int n_in,
                              void* d_out, int out_size)
{
    const int*   ics    = (const int*)d_in[0];
    const float* vals   = (const float*)d_in[1];
    const float* weight = (const float*)d_in[2];
    const float* bias   = (const float*)d_in[3];
    float*       out    = (float*)d_out;

    const int B = in_sizes[0] / K_FEATS;  // 16384

    convert_w16_kernel<<<2048, 256>>>((const float4*)weight);

    dim3 block(32, WARPS_PER_BLOCK);
    dim3 grid(B / ROWS_PER_BLOCK);
    ft_embed_bag_kernel<<<grid, block>>>(ics, vals, bias, out);
}

// round 8
// speedup vs baseline: 1.1604x; 1.1604x over previous
#include <cuda_runtime.h>
#include <cuda_fp16.h>
#include <cstdint>

// Sparse embedding-bag: out[b,:] = bias + sum_k weight[ft_ics[b,k],:] * ft_vals[b,k]
// B=16384, K=32, N_OUT=256. Table 41024x256 fp32 = 42 MB.
//
// R8: fp16-table pre-pass (R5) + gather with KU=8: 32 independent coalesced
// LDG.32 front-batched per phase (4 phases). Plain FMA body (R5's, which beat
// FFMA2/warp-split variants). launch_bounds(256,4) so ptxas can hold the
// 32-wide load batch in registers without spilling.

#define N_IN_ROWS 41024
#define N_OUT_COLS 256
#define K_FEATS 32
#define ROWS_PER_BLOCK 8
#define KU 8

__device__ __half g_w16[(size_t)N_IN_ROWS * N_OUT_COLS];

// ---------------- conversion: fp32 table -> fp16 table (streaming) ----------
__global__ __launch_bounds__(256)
void convert_w16_kernel(const float4* __restrict__ w32)
{
    const size_t n4 = (size_t)N_IN_ROWS * N_OUT_COLS / 4;
    uint2* dst = reinterpret_cast<uint2*>(g_w16);
    for (size_t i = (size_t)blockIdx.x * blockDim.x + threadIdx.x;
         i < n4; i += (size_t)gridDim.x * blockDim.x) {
        const float4 w = __ldg(&w32[i]);
        __half2 h0 = __floats2half2_rn(w.x, w.y);
        __half2 h1 = __floats2half2_rn(w.z, w.w);
        uint2 u;
        u.x = *reinterpret_cast<unsigned*>(&h0);
        u.y = *reinterpret_cast<unsigned*>(&h1);
        dst[i] = u;
    }
}

// ---------------- gather: fp16 table, fp32 accumulate -----------------------
// Warp = one batch row. Lane tx owns column pairs {c*64+2tx, +1 : c=0..3}.
// Each feature row = 128 half2; warp covers it with 4 coalesced LDG.32
// (one 128B line each). KU=8 features front-batched -> 32 loads in flight.
__global__ __launch_bounds__(32 * ROWS_PER_BLOCK, 4)
void ft_embed_bag_kernel(const int* __restrict__ ics,
                         const float* __restrict__ vals,
                         const float* __restrict__ bias,   // [256]
                         float* __restrict__ out)          // [B][256]
{
    __shared__ int   s_idx[ROWS_PER_BLOCK][K_FEATS];
    __shared__ float s_val[ROWS_PER_BLOCK][K_FEATS];

    const int ty = threadIdx.y;
    const int tx = threadIdx.x;
    const int b  = blockIdx.x * ROWS_PER_BLOCK + ty;

    {
        const int   raw = __ldg(&ics[b * K_FEATS + tx]);
        const float v   = __ldg(&vals[b * K_FEATS + tx]);
        const bool valid = (raw >= 0);
        s_idx[ty][tx] = valid ? raw : 0;
        s_val[ty][tx] = valid ? v : 0.0f;
    }
    __syncwarp();

    // acc[2c], acc[2c+1] = output cols c*64 + 2tx, c*64 + 2tx + 1
    float acc[8];
    #pragma unroll
    for (int c = 0; c < 4; ++c) {
        acc[2 * c]     = __ldg(&bias[c * 64 + 2 * tx]);
        acc[2 * c + 1] = __ldg(&bias[c * 64 + 2 * tx + 1]);
    }

    const __half2* wtab = reinterpret_cast<const __half2*>(g_w16);

    #pragma unroll
    for (int k0 = 0; k0 < K_FEATS; k0 += KU) {
        int   idx[KU];
        float v[KU];
        #pragma unroll
        for (int j = 0; j < KU; ++j) {
            idx[j] = s_idx[ty][k0 + j];
            v[j]   = s_val[ty][k0 + j];
        }

        // Front-batch 4*KU = 32 independent coalesced LDG.32 (one line each).
        __half2 w[KU][4];
        #pragma unroll
        for (int j = 0; j < KU; ++j) {
            const __half2* base = wtab + (size_t)idx[j] * 128 + tx;
            #pragma unroll
            for (int c = 0; c < 4; ++c)
                w[j][c] = __ldg(base + c * 32);
        }

        #pragma unroll
        for (int j = 0; j < KU; ++j) {
            #pragma unroll
            for (int c = 0; c < 4; ++c) {
                const float2 wf = __half22float2(w[j][c]);
                acc[2 * c]     = fmaf(v[j], wf.x, acc[2 * c]);
                acc[2 * c + 1] = fmaf(v[j], wf.y, acc[2 * c + 1]);
            }
        }
    }

    // Streaming float2 stores (single-use output).
    float* orow = out + (size_t)b * N_OUT_COLS;
    #pragma unroll
    for (int c = 0; c < 4; ++c) {
        float2 o = make_float2(acc[2 * c], acc[2 * c + 1]);
        __stcs(reinterpret_cast<float2*>(orow + c * 64) + tx, o);
    }
}

extern "C" void kernel_launch(void* const* d_in, const int* in_sizes, int n_in,
                              void* d_out, int out_size)
{
    const int*   ics    = (const int*)d_in[0];
    const float* vals   = (const float*)d_in[1];
    const float* weight = (const float*)d_in[2];
    const float* bias   = (const float*)d_in[3];
    float*       out    = (float*)d_out;

    const int B = in_sizes[0] / K_FEATS;  // 16384

    convert_w16_kernel<<<2048, 256>>>((const float4*)weight);

    dim3 block(32, ROWS_PER_BLOCK);
    dim3 grid(B / ROWS_PER_BLOCK);
    ft_embed_bag_kernel<<<grid, block>>>(ics, vals, bias, out);
}